// round 7
// baseline (speedup 1.0000x reference)
#include <cuda_runtime.h>
#include <cuda_fp16.h>
#include <math.h>

#define NMAX 100000
#define EMAX 3200000

// ---------------- persistent device scratch (no runtime allocation) ----------------
__device__ int     g_csr_src[EMAX];    // src ids grouped by dst
__device__ int     g_deg[NMAX];        // in-degree
__device__ int     g_rowptr[NMAX];     // CSR row starts
__device__ int     g_cur[NMAX];        // scatter cursors
__device__ int     g_bsum[128];        // scan block sums
__device__ int     g_boff[128];        // scan block offsets
// packed per-node payload: 128B block = [32 x fp16 h | as0,as1 fp32 | pad]
__device__ __align__(128) uint4 g_hx[NMAX * 8];
__device__ float   g_S[NMAX * 32];     // aggregation numerator (fp32)
__device__ float   g_ad[NMAX * 2];     // per-node dest attention coeff (fp32)
__device__ float   g_den[NMAX * 2];    // softmax denominator (2-head layers)
__device__ float   g_den1[NMAX];       // softmax denominator (1-head layer)
__device__ int     g_is64;             // edge_index dtype flag

// ---------------- probe dtype + zero the degree histogram (fused) ----------------
__global__ void detect_zero_k(const int* __restrict__ ei32, int N) {
    int i = blockIdx.x * blockDim.x + threadIdx.x;
    if (i < N) g_deg[i] = 0;
    if (i == 0) {
        int acc = 0;
        for (int k = 0; k < 512; k++) acc |= ei32[2 * k + 1];
        g_is64 = (acc == 0) ? 1 : 0;
    }
}

// in-degree histogram straight from edge_index
__global__ void hist_k(const void* __restrict__ ei, int E) {
    int e = blockIdx.x * blockDim.x + threadIdx.x;
    if (e >= E) return;
    int d = g_is64 ? (int)((const long long*)ei)[E + e]
                   : ((const int*)ei)[E + e];
    atomicAdd(&g_deg[d], 1);
}

// ---------------- two-level exclusive scan over degrees -> rowptr ----------------
__global__ void scanA_k(int N) {
    __shared__ int sh[1024];
    const int tid = threadIdx.x;
    const int i = blockIdx.x * 1024 + tid;
    int v = (i < N) ? g_deg[i] : 0;
    sh[tid] = v;
    __syncthreads();
    for (int off = 1; off < 1024; off <<= 1) {
        int t = (tid >= off) ? sh[tid - off] : 0;
        __syncthreads();
        sh[tid] += t;
        __syncthreads();
    }
    if (i < N) g_rowptr[i] = sh[tid] - v;   // exclusive
    if (tid == 1023) g_bsum[blockIdx.x] = sh[tid];
}

__global__ void scanB_k(int nb) {
    __shared__ int sh[128];
    const int tid = threadIdx.x;
    int v = (tid < nb) ? g_bsum[tid] : 0;
    sh[tid] = v;
    __syncthreads();
    for (int off = 1; off < 128; off <<= 1) {
        int t = (tid >= off) ? sh[tid - off] : 0;
        __syncthreads();
        sh[tid] += t;
        __syncthreads();
    }
    if (tid < nb) g_boff[tid] = sh[tid] - v;
}

__global__ void scanC_k(int N) {
    int i = blockIdx.x * blockDim.x + threadIdx.x;
    if (i < N) {
        int r = g_rowptr[i] + g_boff[i >> 10];
        g_rowptr[i] = r;
        g_cur[i] = r;
    }
}

__global__ void scatter_k(const void* __restrict__ ei, int E) {
    int e = blockIdx.x * blockDim.x + threadIdx.x;
    if (e >= E) return;
    int s, d;
    if (g_is64) {
        const long long* p = (const long long*)ei;
        s = (int)p[e];
        d = (int)p[E + e];
    } else {
        const int* p = (const int*)ei;
        s = p[e];
        d = p[E + e];
    }
    int pos = atomicAdd(&g_cur[d], 1);
    g_csr_src[pos] = s;
}

__device__ __forceinline__ unsigned h2u(__half2 h) {
    return *reinterpret_cast<unsigned*>(&h);
}

// ---------------- node kernel: epilogue of prev layer (opt) + transform + att dots
// MODE 0: input = x. MODE 1: after layer1 (scale/1.05/elu/clip). MODE 2: after layer2.
// OH = heads of the NEW layer. Writes packed 128B blocks (fp16 h + fp32 as).
template <int MODE, int OH>
__global__ void node_k(const float* __restrict__ xin,
                       const float* __restrict__ W,
                       const float* __restrict__ att_s,
                       const float* __restrict__ att_d,
                       const float* __restrict__ bias,
                       const float* __restrict__ ea,
                       int N) {
    __shared__ float sh[128 * 33];
    __shared__ float Wsh[1024];      // Wsh[i*32+o] = W[o][i]
    __shared__ float s_att[64];
    __shared__ uint4 sp[128 * 8];    // packed blocks staging

    const int tid  = threadIdx.x;
    const int base = blockIdx.x * 128;
    const int count = min(128, N - base);

    for (int idx = tid; idx < 1024; idx += 128) {
        int o = idx >> 5, i = idx & 31;
        Wsh[i * 32 + o] = W[idx];
    }
    if (tid < 32) { s_att[tid] = att_s[tid]; s_att[32 + tid] = att_d[tid]; }

    for (int idx = tid; idx < count * 32; idx += 128) {
        float v = (MODE == 0) ? xin[base * 32 + idx] : g_S[base * 32 + idx];
        sh[(idx >> 5) * 33 + (idx & 31)] = v;
    }
    __syncthreads();

    const int n = base + tid;
    if (n < N) {
        float* row = &sh[tid * 33];
        if (MODE != 0) {
            const float d0 = g_den[n * 2 + 0] + 1e-16f;
            const float d1 = g_den[n * 2 + 1] + 1e-16f;
            float sc = 1.f;
            if (MODE == 1) {
                float t = tanhf(ea[0]);
                sc = (t < 0.1f) ? 1.f : t;
                sc *= 1.05f;   // h + 0.05*detach(h) == 1.05*h
            }
#pragma unroll
            for (int i = 0; i < 32; i++) {
                float v = row[i] / (i < 16 ? d0 : d1) + bias[i];
                if (MODE == 1) v *= sc;
                v = (v > 0.f) ? v : expm1f(v);         // elu
                v = fminf(3.f, fmaxf(-3.f, v));        // clip
                row[i] = v;
            }
        }
        float acc[32];
#pragma unroll
        for (int o = 0; o < 32; o++) acc[o] = 0.f;
#pragma unroll
        for (int i = 0; i < 32; i++) {
            const float xv = row[i];
#pragma unroll
            for (int o = 0; o < 32; o++) acc[o] += xv * Wsh[i * 32 + o];
        }
        constexpr int CH = 32 / OH;
        float asv[2] = {0.f, 0.f};
#pragma unroll
        for (int h = 0; h < OH; h++) {
            float as = 0.f, ad = 0.f;
#pragma unroll
            for (int c = 0; c < CH; c++) {
                as += acc[h * CH + c] * s_att[h * CH + c];
                ad += acc[h * CH + c] * s_att[32 + h * CH + c];
            }
            asv[h] = as;
            g_ad[n * OH + h] = ad;
        }
        // pack: 4 x uint4 of fp16 h, 1 x uint4 with fp32 as pair, 3 pad
        uint4* myp = &sp[tid * 8];
#pragma unroll
        for (int q = 0; q < 4; q++) {
            myp[q] = make_uint4(
                h2u(__floats2half2_rn(acc[8 * q + 0], acc[8 * q + 1])),
                h2u(__floats2half2_rn(acc[8 * q + 2], acc[8 * q + 3])),
                h2u(__floats2half2_rn(acc[8 * q + 4], acc[8 * q + 5])),
                h2u(__floats2half2_rn(acc[8 * q + 6], acc[8 * q + 7])));
        }
        myp[4] = make_uint4(__float_as_uint(asv[0]), __float_as_uint(asv[1]), 0u, 0u);
        myp[5] = make_uint4(0u, 0u, 0u, 0u);
        myp[6] = make_uint4(0u, 0u, 0u, 0u);
        myp[7] = make_uint4(0u, 0u, 0u, 0u);
    }
    __syncthreads();
    for (int idx = tid; idx < count * 8; idx += 128)
        g_hx[(size_t)base * 8 + idx] = sp[idx];
}

// ---------------- warp-per-node aggregation on packed blocks -------------------
// 4 edge-slots x 8 lanes. Per edge: eslot's 8 lanes issue ONE uint4 LDG covering
// the node's 128B block (h fp16 + as fp32 in the same line). Lanes j<4 own 8
// channels each; as reaches them via 2 shfls from lane (eslot*8+4). No atomics.
template <int H>
__global__ void agg_warp_k(int N, float slope, int E) {
    const int warp = (blockIdx.x * blockDim.x + threadIdx.x) >> 5;
    if (warp >= N) return;                 // uniform per warp
    const int lane  = threadIdx.x & 31;
    const int eslot = lane >> 3;           // 0..3
    const int j     = lane & 7;
    const int head  = (H == 2) ? ((j >> 1) & 1) : 0;
    const int asrc  = (lane & 24) + 4;     // lane holding as within this eslot
    const int joff  = (j < 5) ? j : 4;     // lanes 5-7 mirror lane 4 (same sector)

    const int beg = g_rowptr[warp];
    const int deg = g_deg[warp];
    const float adh = g_ad[warp * H + head];

    float acc[8];
#pragma unroll
    for (int c = 0; c < 8; c++) acc[c] = 0.f;
    float den = 0.f;

    for (int b = 0; b < deg; b += 32) {
        int idx = beg + b + lane;
        if (idx >= E) idx = E - 1;         // clamp: lanes past row end unused
        const int sb = g_csr_src[idx];
        const int nIt = min(32, deg - b);
        for (int step = 0; step * 4 < nIt; ++step) {
            const int q = step * 4 + eslot;
            const int s = __shfl_sync(0xffffffffu, sb, q & 31);
            const bool act = (q < nIt);
            uint4 ld = make_uint4(0u, 0u, 0u, 0u);
            if (act) ld = g_hx[(size_t)s * 8 + joff];
            const unsigned a0 = __shfl_sync(0xffffffffu, ld.x, asrc);
            const unsigned a1 = __shfl_sync(0xffffffffu, ld.y, asrc);
            if (act && j < 4) {
                float l = __uint_as_float((H == 2 && head) ? a1 : a0) + adh;
                l = (l > 0.f) ? l : l * slope;
                const float ex = __expf(l);
                float2 f;
                f = __half22float2(*reinterpret_cast<__half2*>(&ld.x));
                acc[0] += ex * f.x; acc[1] += ex * f.y;
                f = __half22float2(*reinterpret_cast<__half2*>(&ld.y));
                acc[2] += ex * f.x; acc[3] += ex * f.y;
                f = __half22float2(*reinterpret_cast<__half2*>(&ld.z));
                acc[4] += ex * f.x; acc[5] += ex * f.y;
                f = __half22float2(*reinterpret_cast<__half2*>(&ld.w));
                acc[6] += ex * f.x; acc[7] += ex * f.y;
                den += ex;
            }
        }
    }
    // combine the 4 eslots (lanes 0-3 of each eslot pair across xor 8,16)
#pragma unroll
    for (int k = 8; k < 32; k <<= 1) {
#pragma unroll
        for (int c = 0; c < 8; c++)
            acc[c] += __shfl_xor_sync(0xffffffffu, acc[c], k);
        den += __shfl_xor_sync(0xffffffffu, den, k);
    }

    if (eslot == 0 && j < 4) {
        *reinterpret_cast<float4*>(&g_S[(size_t)warp * 32 + j * 8]) =
            make_float4(acc[0], acc[1], acc[2], acc[3]);
        *reinterpret_cast<float4*>(&g_S[(size_t)warp * 32 + j * 8 + 4]) =
            make_float4(acc[4], acc[5], acc[6], acc[7]);
        if (H == 2) {
            if (j == 0) g_den[warp * 2 + 0] = den;  // lanes 0,1 held head0's ex
            if (j == 2) g_den[warp * 2 + 1] = den;  // lanes 2,3 held head1's ex
        } else {
            if (j == 0) g_den1[warp] = den;
        }
    }
}

// ---------------- final epilogue: layer-3 normalize + bias ----------------
__global__ void final_k(const float* __restrict__ b3, float* __restrict__ out, int N) {
    int idx = blockIdx.x * blockDim.x + threadIdx.x;
    if (idx < N * 32)
        out[idx] = g_S[idx] / (g_den1[idx >> 5] + 1e-16f) + b3[idx & 31];
}

extern "C" void kernel_launch(void* const* d_in, const int* in_sizes, int n_in,
                              void* d_out, int out_size) {
    const float* x   = (const float*)d_in[0];
    const void*  ei  = d_in[1];
    const float* W1  = (const float*)d_in[2];
    const float* as1 = (const float*)d_in[3];
    const float* ad1 = (const float*)d_in[4];
    const float* b1  = (const float*)d_in[5];
    const float* ea1 = (const float*)d_in[6];
    const float* W2  = (const float*)d_in[7];
    const float* as2 = (const float*)d_in[8];
    const float* ad2 = (const float*)d_in[9];
    const float* b2  = (const float*)d_in[10];
    const float* W3  = (const float*)d_in[11];
    const float* as3 = (const float*)d_in[12];
    const float* ad3 = (const float*)d_in[13];
    const float* b3  = (const float*)d_in[14];
    float* out = (float*)d_out;

    const int N  = in_sizes[0] / 32;
    const int E  = in_sizes[1] / 2;
    const int nb = (N + 127) / 128;
    const int eb = (E + 255) / 256;
    const int wb = (int)(((long long)N * 32 + 255) / 256);
    const int sb = (N + 1023) / 1024;

    // ---- one-time CSR build (topology shared by all 3 layers) ----
    detect_zero_k<<<(N + 255) / 256, 256>>>((const int*)ei, N);
    hist_k<<<eb, 256>>>(ei, E);
    scanA_k<<<sb, 1024>>>(N);
    scanB_k<<<1, 128>>>(sb);
    scanC_k<<<(N + 255) / 256, 256>>>(N);
    scatter_k<<<eb, 256>>>(ei, E);

    // ---- layer 1 (slope 0.01, H=2) ----
    node_k<0, 2><<<nb, 128>>>(x, W1, as1, ad1, nullptr, nullptr, N);
    agg_warp_k<2><<<wb, 256>>>(N, 0.01f, E);

    // ---- layer 2 (slope 0.2, H=2) ----
    node_k<1, 2><<<nb, 128>>>(nullptr, W2, as2, ad2, b1, ea1, N);
    agg_warp_k<2><<<wb, 256>>>(N, 0.2f, E);

    // ---- layer 3 (slope 0.2, H=1) ----
    node_k<2, 1><<<nb, 128>>>(nullptr, W3, as3, ad3, b2, nullptr, N);
    agg_warp_k<1><<<wb, 256>>>(N, 0.2f, E);

    final_k<<<(N * 32 + 255) / 256, 256>>>(b3, out, N);
}

// round 8
// speedup vs baseline: 1.1097x; 1.1097x over previous
#include <cuda_runtime.h>
#include <cuda_fp16.h>
#include <math.h>

#define NMAX 100000
#define EMAX 3200000

// ---------------- persistent device scratch (no runtime allocation) ----------------
__device__ int     g_csr_src[EMAX];    // src ids grouped by dst
__device__ int     g_deg[NMAX];        // in-degree
__device__ int     g_rowptr[NMAX];     // CSR row starts
__device__ int     g_cur[NMAX];        // scatter cursors
__device__ int     g_bsum[128];        // scan block sums
__device__ int     g_boff[128];        // scan block offsets
// packed per-node payload: 128B block = [32 x fp16 h | as0,as1 fp32 | pad]
__device__ __align__(128) uint4 g_hx[NMAX * 8];
__device__ float   g_S[NMAX * 32];     // aggregation numerator (fp32)
__device__ float   g_ad[NMAX * 2];     // per-node dest attention coeff (fp32)
__device__ float   g_den[NMAX * 2];    // softmax denominator (2-head layers)
__device__ float   g_den1[NMAX];       // softmax denominator (1-head layer)
__device__ int     g_is64;             // edge_index dtype flag

// ---------------- probe dtype + zero the degree histogram (fused) ----------------
__global__ void detect_zero_k(const int* __restrict__ ei32, int N) {
    int i = blockIdx.x * blockDim.x + threadIdx.x;
    if (i < N) g_deg[i] = 0;
    if (i == 0) {
        int acc = 0;
        for (int k = 0; k < 512; k++) acc |= ei32[2 * k + 1];
        g_is64 = (acc == 0) ? 1 : 0;
    }
}

// in-degree histogram straight from edge_index
__global__ void hist_k(const void* __restrict__ ei, int E) {
    int e = blockIdx.x * blockDim.x + threadIdx.x;
    if (e >= E) return;
    int d = g_is64 ? (int)((const long long*)ei)[E + e]
                   : ((const int*)ei)[E + e];
    atomicAdd(&g_deg[d], 1);
}

// ---------------- two-level exclusive scan over degrees -> rowptr ----------------
__global__ void scanA_k(int N) {
    __shared__ int sh[1024];
    const int tid = threadIdx.x;
    const int i = blockIdx.x * 1024 + tid;
    int v = (i < N) ? g_deg[i] : 0;
    sh[tid] = v;
    __syncthreads();
    for (int off = 1; off < 1024; off <<= 1) {
        int t = (tid >= off) ? sh[tid - off] : 0;
        __syncthreads();
        sh[tid] += t;
        __syncthreads();
    }
    if (i < N) g_rowptr[i] = sh[tid] - v;   // exclusive
    if (tid == 1023) g_bsum[blockIdx.x] = sh[tid];
}

__global__ void scanB_k(int nb) {
    __shared__ int sh[128];
    const int tid = threadIdx.x;
    int v = (tid < nb) ? g_bsum[tid] : 0;
    sh[tid] = v;
    __syncthreads();
    for (int off = 1; off < 128; off <<= 1) {
        int t = (tid >= off) ? sh[tid - off] : 0;
        __syncthreads();
        sh[tid] += t;
        __syncthreads();
    }
    if (tid < nb) g_boff[tid] = sh[tid] - v;
}

__global__ void scanC_k(int N) {
    int i = blockIdx.x * blockDim.x + threadIdx.x;
    if (i < N) {
        int r = g_rowptr[i] + g_boff[i >> 10];
        g_rowptr[i] = r;
        g_cur[i] = r;
    }
}

__global__ void scatter_k(const void* __restrict__ ei, int E) {
    int e = blockIdx.x * blockDim.x + threadIdx.x;
    if (e >= E) return;
    int s, d;
    if (g_is64) {
        const long long* p = (const long long*)ei;
        s = (int)p[e];
        d = (int)p[E + e];
    } else {
        const int* p = (const int*)ei;
        s = p[e];
        d = p[E + e];
    }
    int pos = atomicAdd(&g_cur[d], 1);
    g_csr_src[pos] = s;
}

__device__ __forceinline__ unsigned h2u(__half2 h) {
    return *reinterpret_cast<unsigned*>(&h);
}

// ---------------- node kernel: epilogue of prev layer (opt) + transform + att dots
// MODE 0: input = x. MODE 1: after layer1 (scale/1.05/elu/clip). MODE 2: after layer2.
// OH = heads of the NEW layer. Writes packed 128B blocks (fp16 h + fp32 as).
template <int MODE, int OH>
__global__ void node_k(const float* __restrict__ xin,
                       const float* __restrict__ W,
                       const float* __restrict__ att_s,
                       const float* __restrict__ att_d,
                       const float* __restrict__ bias,
                       const float* __restrict__ ea,
                       int N) {
    __shared__ float sh[128 * 33];
    __shared__ float Wsh[1024];      // Wsh[i*32+o] = W[o][i]
    __shared__ float s_att[64];
    __shared__ uint4 sp[128 * 8];    // packed blocks staging

    const int tid  = threadIdx.x;
    const int base = blockIdx.x * 128;
    const int count = min(128, N - base);

    for (int idx = tid; idx < 1024; idx += 128) {
        int o = idx >> 5, i = idx & 31;
        Wsh[i * 32 + o] = W[idx];
    }
    if (tid < 32) { s_att[tid] = att_s[tid]; s_att[32 + tid] = att_d[tid]; }

    for (int idx = tid; idx < count * 32; idx += 128) {
        float v = (MODE == 0) ? xin[base * 32 + idx] : g_S[base * 32 + idx];
        sh[(idx >> 5) * 33 + (idx & 31)] = v;
    }
    __syncthreads();

    const int n = base + tid;
    if (n < N) {
        float* row = &sh[tid * 33];
        if (MODE != 0) {
            const float d0 = g_den[n * 2 + 0] + 1e-16f;
            const float d1 = g_den[n * 2 + 1] + 1e-16f;
            float sc = 1.f;
            if (MODE == 1) {
                float t = tanhf(ea[0]);
                sc = (t < 0.1f) ? 1.f : t;
                sc *= 1.05f;   // h + 0.05*detach(h) == 1.05*h
            }
#pragma unroll
            for (int i = 0; i < 32; i++) {
                float v = row[i] / (i < 16 ? d0 : d1) + bias[i];
                if (MODE == 1) v *= sc;
                v = (v > 0.f) ? v : expm1f(v);         // elu
                v = fminf(3.f, fmaxf(-3.f, v));        // clip
                row[i] = v;
            }
        }
        float acc[32];
#pragma unroll
        for (int o = 0; o < 32; o++) acc[o] = 0.f;
#pragma unroll
        for (int i = 0; i < 32; i++) {
            const float xv = row[i];
#pragma unroll
            for (int o = 0; o < 32; o++) acc[o] += xv * Wsh[i * 32 + o];
        }
        constexpr int CH = 32 / OH;
        float asv[2] = {0.f, 0.f};
#pragma unroll
        for (int h = 0; h < OH; h++) {
            float as = 0.f, ad = 0.f;
#pragma unroll
            for (int c = 0; c < CH; c++) {
                as += acc[h * CH + c] * s_att[h * CH + c];
                ad += acc[h * CH + c] * s_att[32 + h * CH + c];
            }
            asv[h] = as;
            g_ad[n * OH + h] = ad;
        }
        // pack: 4 x uint4 of fp16 h, 1 x uint4 with fp32 as pair, pads
        uint4* myp = &sp[tid * 8];
#pragma unroll
        for (int q = 0; q < 4; q++) {
            myp[q] = make_uint4(
                h2u(__floats2half2_rn(acc[8 * q + 0], acc[8 * q + 1])),
                h2u(__floats2half2_rn(acc[8 * q + 2], acc[8 * q + 3])),
                h2u(__floats2half2_rn(acc[8 * q + 4], acc[8 * q + 5])),
                h2u(__floats2half2_rn(acc[8 * q + 6], acc[8 * q + 7])));
        }
        myp[4] = make_uint4(__float_as_uint(asv[0]), __float_as_uint(asv[1]), 0u, 0u);
        myp[5] = make_uint4(0u, 0u, 0u, 0u);
        myp[6] = make_uint4(0u, 0u, 0u, 0u);
        myp[7] = make_uint4(0u, 0u, 0u, 0u);
    }
    __syncthreads();
    for (int idx = tid; idx < count * 8; idx += 128)
        g_hx[(size_t)base * 8 + idx] = sp[idx];
}

// ---------------- warp-per-node aggregation, merged single-line gather ------------
// R5 skeleton (flat loop, 4 eslots), but per edge the eslot's 8 lanes issue ONE
// uint4 LDG into the node's 128B block: lanes j<4 get 8 fp16 channels each,
// lanes 4-7 get the (as0,as1) sector; 2 shfls broadcast as within the eslot.
// Uniform trip count + SEL predication keeps shfls converged. No atomics.
template <int H>
__global__ void agg_warp_k(int N, float slope) {
    const int warp = (blockIdx.x * blockDim.x + threadIdx.x) >> 5;
    if (warp >= N) return;                 // uniform per warp
    const int lane  = threadIdx.x & 31;
    const int eslot = lane >> 3;           // 0..3
    const int j     = lane & 7;
    const int head  = (H == 2) ? ((j >> 1) & 1) : 0;
    const int asrc  = (lane & 24) + 4;     // lane holding the as sector in this eslot
    const int joff  = (j < 4) ? j : 4;     // lanes 5-7 mirror lane 4's 16B

    const int beg = g_rowptr[warp];
    const int deg = g_deg[warp];
    const float adh = g_ad[warp * H + head];

    float acc[8];
#pragma unroll
    for (int c = 0; c < 8; c++) acc[c] = 0.f;
    float den = 0.f;

    const int iters = (deg + 3) >> 2;      // warp-uniform
#pragma unroll 4
    for (int t = 0; t < iters; t++) {
        const int i = t * 4 + eslot;
        const bool act = (i < deg);
        const int s = g_csr_src[beg + (act ? i : 0)];   // safe: deg>0 here
        const uint4 ld = g_hx[(size_t)s * 8 + joff];
        const float a0 = __uint_as_float(__shfl_sync(0xffffffffu, ld.x, asrc));
        const float a1 = __uint_as_float(__shfl_sync(0xffffffffu, ld.y, asrc));
        float l = ((H == 2) && head ? a1 : a0) + adh;
        l = (l > 0.f) ? l : l * slope;
        const float ex = act ? __expf(l) : 0.f;
        float2 f;
        f = __half22float2(*reinterpret_cast<const __half2*>(&ld.x));
        acc[0] += ex * f.x; acc[1] += ex * f.y;
        f = __half22float2(*reinterpret_cast<const __half2*>(&ld.y));
        acc[2] += ex * f.x; acc[3] += ex * f.y;
        f = __half22float2(*reinterpret_cast<const __half2*>(&ld.z));
        acc[4] += ex * f.x; acc[5] += ex * f.y;
        f = __half22float2(*reinterpret_cast<const __half2*>(&ld.w));
        acc[6] += ex * f.x; acc[7] += ex * f.y;
        den += ex;
    }
    // combine the 4 eslots: xor 8,16 keeps j fixed, mixes eslots only
#pragma unroll
    for (int k = 8; k < 32; k <<= 1) {
#pragma unroll
        for (int c = 0; c < 8; c++)
            acc[c] += __shfl_xor_sync(0xffffffffu, acc[c], k);
        den += __shfl_xor_sync(0xffffffffu, den, k);
    }

    if (eslot == 0 && j < 4) {
        *reinterpret_cast<float4*>(&g_S[(size_t)warp * 32 + j * 8]) =
            make_float4(acc[0], acc[1], acc[2], acc[3]);
        *reinterpret_cast<float4*>(&g_S[(size_t)warp * 32 + j * 8 + 4]) =
            make_float4(acc[4], acc[5], acc[6], acc[7]);
        if (H == 2) {
            if (j == 0) g_den[warp * 2 + 0] = den;  // lanes 0,1 accumulated head0 ex
            if (j == 2) g_den[warp * 2 + 1] = den;  // lanes 2,3 accumulated head1 ex
        } else {
            if (j == 0) g_den1[warp] = den;
        }
    }
}

// ---------------- final epilogue: layer-3 normalize + bias ----------------
__global__ void final_k(const float* __restrict__ b3, float* __restrict__ out, int N) {
    int idx = blockIdx.x * blockDim.x + threadIdx.x;
    if (idx < N * 32)
        out[idx] = g_S[idx] / (g_den1[idx >> 5] + 1e-16f) + b3[idx & 31];
}

extern "C" void kernel_launch(void* const* d_in, const int* in_sizes, int n_in,
                              void* d_out, int out_size) {
    const float* x   = (const float*)d_in[0];
    const void*  ei  = d_in[1];
    const float* W1  = (const float*)d_in[2];
    const float* as1 = (const float*)d_in[3];
    const float* ad1 = (const float*)d_in[4];
    const float* b1  = (const float*)d_in[5];
    const float* ea1 = (const float*)d_in[6];
    const float* W2  = (const float*)d_in[7];
    const float* as2 = (const float*)d_in[8];
    const float* ad2 = (const float*)d_in[9];
    const float* b2  = (const float*)d_in[10];
    const float* W3  = (const float*)d_in[11];
    const float* as3 = (const float*)d_in[12];
    const float* ad3 = (const float*)d_in[13];
    const float* b3  = (const float*)d_in[14];
    float* out = (float*)d_out;

    const int N  = in_sizes[0] / 32;
    const int E  = in_sizes[1] / 2;
    const int nb = (N + 127) / 128;
    const int eb = (E + 255) / 256;
    const int wb = (int)(((long long)N * 32 + 255) / 256);
    const int sb = (N + 1023) / 1024;

    // ---- one-time CSR build (topology shared by all 3 layers) ----
    detect_zero_k<<<(N + 255) / 256, 256>>>((const int*)ei, N);
    hist_k<<<eb, 256>>>(ei, E);
    scanA_k<<<sb, 1024>>>(N);
    scanB_k<<<1, 128>>>(sb);
    scanC_k<<<(N + 255) / 256, 256>>>(N);
    scatter_k<<<eb, 256>>>(ei, E);

    // ---- layer 1 (slope 0.01, H=2) ----
    node_k<0, 2><<<nb, 128>>>(x, W1, as1, ad1, nullptr, nullptr, N);
    agg_warp_k<2><<<wb, 256>>>(N, 0.01f);

    // ---- layer 2 (slope 0.2, H=2) ----
    node_k<1, 2><<<nb, 128>>>(nullptr, W2, as2, ad2, b1, ea1, N);
    agg_warp_k<2><<<wb, 256>>>(N, 0.2f);

    // ---- layer 3 (slope 0.2, H=1) ----
    node_k<2, 1><<<nb, 128>>>(nullptr, W3, as3, ad3, b2, nullptr, N);
    agg_warp_k<1><<<wb, 256>>>(N, 0.2f);

    final_k<<<(N * 32 + 255) / 256, 256>>>(b3, out, N);
}

// round 9
// speedup vs baseline: 1.3848x; 1.2480x over previous
#include <cuda_runtime.h>
#include <cuda_fp16.h>
#include <math.h>

#define NMAX 100000
#define EMAX 3200000

// ---------------- persistent device scratch (no runtime allocation) ----------------
__device__ int     g_src[EMAX];
__device__ int     g_dst[EMAX];
__device__ int     g_csr_src[EMAX];    // src ids grouped by dst
__device__ int     g_deg[NMAX];        // in-degree
__device__ int     g_rowptr[NMAX];     // CSR row starts
__device__ int     g_cur[NMAX];        // scatter cursors
__device__ int     g_bsum[128];        // scan block sums
__device__ int     g_boff[128];        // scan block offsets
// packed per-node payload: 8 x 16B chunks; chunk j = [4 x fp16 h(4j..4j+3) | as0 | as1]
__device__ __align__(128) uint4 g_hx[NMAX * 8];
__device__ float   g_S[NMAX * 32];     // aggregation numerator (fp32)
__device__ float   g_ad[NMAX * 2];     // per-node dest attention coeff (fp32)
__device__ float   g_den[NMAX * 2];    // softmax denominator (2-head layers)
__device__ float   g_den1[NMAX];       // softmax denominator (1-head layer)
__device__ int     g_is64;             // edge_index dtype flag

// ---------------- probe dtype + zero the degree histogram (fused) ----------------
__global__ void detect_zero_k(const int* __restrict__ ei32, int N) {
    int i = blockIdx.x * blockDim.x + threadIdx.x;
    if (i < N) g_deg[i] = 0;
    if (i == 0) {
        int acc = 0;
        for (int k = 0; k < 512; k++) acc |= ei32[2 * k + 1];
        g_is64 = (acc == 0) ? 1 : 0;
    }
}

// convert edge index to int32 + in-degree histogram
__global__ void convert_k(const void* __restrict__ ei, int E) {
    int e = blockIdx.x * blockDim.x + threadIdx.x;
    if (e >= E) return;
    int s, d;
    if (g_is64) {
        const long long* p = (const long long*)ei;
        s = (int)p[e];
        d = (int)p[E + e];
    } else {
        const int* p = (const int*)ei;
        s = p[e];
        d = p[E + e];
    }
    g_src[e] = s;
    g_dst[e] = d;
    atomicAdd(&g_deg[d], 1);
}

// ---------------- two-level exclusive scan over degrees -> rowptr ----------------
__global__ void scanA_k(int N) {
    __shared__ int sh[1024];
    const int tid = threadIdx.x;
    const int i = blockIdx.x * 1024 + tid;
    int v = (i < N) ? g_deg[i] : 0;
    sh[tid] = v;
    __syncthreads();
    for (int off = 1; off < 1024; off <<= 1) {
        int t = (tid >= off) ? sh[tid - off] : 0;
        __syncthreads();
        sh[tid] += t;
        __syncthreads();
    }
    if (i < N) g_rowptr[i] = sh[tid] - v;   // exclusive
    if (tid == 1023) g_bsum[blockIdx.x] = sh[tid];
}

__global__ void scanB_k(int nb) {
    __shared__ int sh[128];
    const int tid = threadIdx.x;
    int v = (tid < nb) ? g_bsum[tid] : 0;
    sh[tid] = v;
    __syncthreads();
    for (int off = 1; off < 128; off <<= 1) {
        int t = (tid >= off) ? sh[tid - off] : 0;
        __syncthreads();
        sh[tid] += t;
        __syncthreads();
    }
    if (tid < nb) g_boff[tid] = sh[tid] - v;
}

__global__ void scanC_k(int N) {
    int i = blockIdx.x * blockDim.x + threadIdx.x;
    if (i < N) {
        int r = g_rowptr[i] + g_boff[i >> 10];
        g_rowptr[i] = r;
        g_cur[i] = r;
    }
}

__global__ void scatter_k(int E) {
    int e = blockIdx.x * blockDim.x + threadIdx.x;
    if (e >= E) return;
    int pos = atomicAdd(&g_cur[g_dst[e]], 1);
    g_csr_src[pos] = g_src[e];
}

__device__ __forceinline__ unsigned h2u(__half2 h) {
    return *reinterpret_cast<unsigned*>(&h);
}

// ---------------- node kernel: epilogue of prev layer (opt) + transform + att dots
// MODE 0: input = x. MODE 1: after layer1 (scale/1.05/elu/clip). MODE 2: after layer2.
// OH = heads of the NEW layer. Writes 8x16B self-contained chunks per node:
// chunk j = [half2(c4j,c4j+1), half2(c4j+2,c4j+3), as0_fp32, as1_fp32].
template <int MODE, int OH>
__global__ void node_k(const float* __restrict__ xin,
                       const float* __restrict__ W,
                       const float* __restrict__ att_s,
                       const float* __restrict__ att_d,
                       const float* __restrict__ bias,
                       const float* __restrict__ ea,
                       int N) {
    __shared__ float sh[128 * 33];
    __shared__ float Wsh[1024];      // Wsh[i*32+o] = W[o][i]
    __shared__ float s_att[64];
    __shared__ uint4 sp[128 * 8];    // packed chunks staging

    const int tid  = threadIdx.x;
    const int base = blockIdx.x * 128;
    const int count = min(128, N - base);

    for (int idx = tid; idx < 1024; idx += 128) {
        int o = idx >> 5, i = idx & 31;
        Wsh[i * 32 + o] = W[idx];
    }
    if (tid < 32) { s_att[tid] = att_s[tid]; s_att[32 + tid] = att_d[tid]; }

    for (int idx = tid; idx < count * 32; idx += 128) {
        float v = (MODE == 0) ? xin[base * 32 + idx] : g_S[base * 32 + idx];
        sh[(idx >> 5) * 33 + (idx & 31)] = v;
    }
    __syncthreads();

    const int n = base + tid;
    if (n < N) {
        float* row = &sh[tid * 33];
        if (MODE != 0) {
            const float d0 = g_den[n * 2 + 0] + 1e-16f;
            const float d1 = g_den[n * 2 + 1] + 1e-16f;
            float sc = 1.f;
            if (MODE == 1) {
                float t = tanhf(ea[0]);
                sc = (t < 0.1f) ? 1.f : t;
                sc *= 1.05f;   // h + 0.05*detach(h) == 1.05*h
            }
#pragma unroll
            for (int i = 0; i < 32; i++) {
                float v = row[i] / (i < 16 ? d0 : d1) + bias[i];
                if (MODE == 1) v *= sc;
                v = (v > 0.f) ? v : expm1f(v);         // elu
                v = fminf(3.f, fmaxf(-3.f, v));        // clip
                row[i] = v;
            }
        }
        float acc[32];
#pragma unroll
        for (int o = 0; o < 32; o++) acc[o] = 0.f;
#pragma unroll
        for (int i = 0; i < 32; i++) {
            const float xv = row[i];
#pragma unroll
            for (int o = 0; o < 32; o++) acc[o] += xv * Wsh[i * 32 + o];
        }
        constexpr int CH = 32 / OH;
        float asv[2] = {0.f, 0.f};
#pragma unroll
        for (int h = 0; h < OH; h++) {
            float as = 0.f, ad = 0.f;
#pragma unroll
            for (int c = 0; c < CH; c++) {
                as += acc[h * CH + c] * s_att[h * CH + c];
                ad += acc[h * CH + c] * s_att[32 + h * CH + c];
            }
            asv[h] = as;
            g_ad[n * OH + h] = ad;
        }
        // pack 8 self-contained chunks: 4 fp16 channels + fp32 as pair each
        uint4* myp = &sp[tid * 8];
        const unsigned ua0 = __float_as_uint(asv[0]);
        const unsigned ua1 = __float_as_uint(asv[1]);
#pragma unroll
        for (int q = 0; q < 8; q++) {
            myp[q] = make_uint4(
                h2u(__floats2half2_rn(acc[4 * q + 0], acc[4 * q + 1])),
                h2u(__floats2half2_rn(acc[4 * q + 2], acc[4 * q + 3])),
                ua0, ua1);
        }
    }
    __syncthreads();
    for (int idx = tid; idx < count * 8; idx += 128)
        g_hx[(size_t)base * 8 + idx] = sp[idx];
}

// ---------------- warp-per-node aggregation, self-contained 16B gathers ----------
// R5/R6 skeleton: 4 edge-slots x 8 channel-lanes, per-lane independent loop,
// ZERO warp communication inside the loop. Per edge, lane j issues one uint4
// LDG: its 4 fp16 channels + the fp32 as pair (replicated in every chunk).
// Per 4-edge iter: 1 csr line + 4 block lines. Combine = shfl-ADD after loop.
template <int H>
__global__ void agg_warp_k(int N, float slope) {
    const int warp = (blockIdx.x * blockDim.x + threadIdx.x) >> 5;
    if (warp >= N) return;                 // uniform per warp
    const int lane  = threadIdx.x & 31;
    const int eslot = lane >> 3;           // 0..3
    const int j     = lane & 7;            // channel chunk (4 channels)
    const int head  = (H == 2) ? (j >> 2) : 0;

    const int beg = g_rowptr[warp];
    const int deg = g_deg[warp];
    const float adh = g_ad[warp * H + head];

    float4 acc = make_float4(0.f, 0.f, 0.f, 0.f);
    float den = 0.f;
#pragma unroll 4
    for (int i = eslot; i < deg; i += 4) {
        const int s = __ldg(&g_csr_src[beg + i]);
        const uint4 ld = g_hx[(size_t)s * 8 + j];
        float l = __uint_as_float(head ? ld.w : ld.z) + adh;
        l = (l > 0.f) ? l : l * slope;
        const float ex = __expf(l);
        const float2 f0 = __half22float2(*reinterpret_cast<const __half2*>(&ld.x));
        const float2 f1 = __half22float2(*reinterpret_cast<const __half2*>(&ld.y));
        acc.x += ex * f0.x;
        acc.y += ex * f0.y;
        acc.z += ex * f1.x;
        acc.w += ex * f1.y;
        den += ex;
    }
    // combine eslots: xor 8,16 keeps j (channels/head) fixed, mixes eslots only
#pragma unroll
    for (int k = 8; k < 32; k <<= 1) {
        acc.x += __shfl_xor_sync(0xffffffffu, acc.x, k);
        acc.y += __shfl_xor_sync(0xffffffffu, acc.y, k);
        acc.z += __shfl_xor_sync(0xffffffffu, acc.z, k);
        acc.w += __shfl_xor_sync(0xffffffffu, acc.w, k);
        den   += __shfl_xor_sync(0xffffffffu, den, k);
    }

    if (eslot == 0) {
        *reinterpret_cast<float4*>(&g_S[(size_t)warp * 32 + j * 4]) = acc;
        if (H == 2) {
            if (j == 0) g_den[warp * 2 + 0] = den;
            if (j == 4) g_den[warp * 2 + 1] = den;
        } else {
            if (j == 0) g_den1[warp] = den;
        }
    }
}

// ---------------- final epilogue: layer-3 normalize + bias ----------------
__global__ void final_k(const float* __restrict__ b3, float* __restrict__ out, int N) {
    int idx = blockIdx.x * blockDim.x + threadIdx.x;
    if (idx < N * 32)
        out[idx] = g_S[idx] / (g_den1[idx >> 5] + 1e-16f) + b3[idx & 31];
}

extern "C" void kernel_launch(void* const* d_in, const int* in_sizes, int n_in,
                              void* d_out, int out_size) {
    const float* x   = (const float*)d_in[0];
    const void*  ei  = d_in[1];
    const float* W1  = (const float*)d_in[2];
    const float* as1 = (const float*)d_in[3];
    const float* ad1 = (const float*)d_in[4];
    const float* b1  = (const float*)d_in[5];
    const float* ea1 = (const float*)d_in[6];
    const float* W2  = (const float*)d_in[7];
    const float* as2 = (const float*)d_in[8];
    const float* ad2 = (const float*)d_in[9];
    const float* b2  = (const float*)d_in[10];
    const float* W3  = (const float*)d_in[11];
    const float* as3 = (const float*)d_in[12];
    const float* ad3 = (const float*)d_in[13];
    const float* b3  = (const float*)d_in[14];
    float* out = (float*)d_out;

    const int N  = in_sizes[0] / 32;
    const int E  = in_sizes[1] / 2;
    const int nb = (N + 127) / 128;
    const int eb = (E + 255) / 256;
    const int wb = (int)(((long long)N * 32 + 255) / 256);
    const int sb = (N + 1023) / 1024;

    // ---- one-time CSR build (topology shared by all 3 layers) ----
    detect_zero_k<<<(N + 255) / 256, 256>>>((const int*)ei, N);
    convert_k<<<eb, 256>>>(ei, E);
    scanA_k<<<sb, 1024>>>(N);
    scanB_k<<<1, 128>>>(sb);
    scanC_k<<<(N + 255) / 256, 256>>>(N);
    scatter_k<<<eb, 256>>>(E);

    // ---- layer 1 (slope 0.01, H=2) ----
    node_k<0, 2><<<nb, 128>>>(x, W1, as1, ad1, nullptr, nullptr, N);
    agg_warp_k<2><<<wb, 256>>>(N, 0.01f);

    // ---- layer 2 (slope 0.2, H=2) ----
    node_k<1, 2><<<nb, 128>>>(nullptr, W2, as2, ad2, b1, ea1, N);
    agg_warp_k<2><<<wb, 256>>>(N, 0.2f);

    // ---- layer 3 (slope 0.2, H=1) ----
    node_k<2, 1><<<nb, 128>>>(nullptr, W3, as3, ad3, b2, nullptr, N);
    agg_warp_k<1><<<wb, 256>>>(N, 0.2f);

    final_k<<<(N * 32 + 255) / 256, 256>>>(b3, out, N);
}